// round 12
// baseline (speedup 1.0000x reference)
#include <cuda_runtime.h>
#include <cstdint>

#define NB  8
#define SEQ 2048
#define HID 256
#define BM  64
#define BN  256
#define QKSCALE 0.0625f

typedef unsigned long long ull;

__device__ __forceinline__ uint32_t smem_u32(const void* p){
    uint32_t a;
    asm("{ .reg .u64 t; cvta.to.shared.u64 t, %1; cvt.u32.u64 %0, t; }" : "=r"(a) : "l"(p));
    return a;
}
// round fp32 -> tf32 (RN, unbiased)
__device__ __forceinline__ float tf32r(float x){
    uint32_t u; asm("cvt.rna.tf32.f32 %0, %1;" : "=r"(u) : "f"(x));
    return __uint_as_float(u);
}
__device__ __forceinline__ uint32_t tf32u(float x){
    uint32_t u; asm("cvt.rna.tf32.f32 %0, %1;" : "=r"(u) : "f"(x));
    return u;
}
#define CPASYNC16(dst, src) \
    asm volatile("cp.async.cg.shared.global [%0], [%1], 16;" :: "r"(dst), "l"(src) : "memory")
#define CP_COMMIT()  asm volatile("cp.async.commit_group;" ::: "memory")
#define CP_WAIT(n)   asm volatile("cp.async.wait_group %0;" :: "n"(n) : "memory")

// m16n8k8 tf32 mma
__device__ __forceinline__ void mma8(float* c,
    uint32_t a0, uint32_t a1, uint32_t a2, uint32_t a3, uint32_t b0, uint32_t b1)
{
    asm volatile("mma.sync.aligned.m16n8k8.row.col.f32.tf32.tf32.f32 "
        "{%0,%1,%2,%3}, {%4,%5,%6,%7}, {%8,%9}, {%0,%1,%2,%3};"
        : "+f"(c[0]), "+f"(c[1]), "+f"(c[2]), "+f"(c[3])
        : "r"(a0), "r"(a1), "r"(a2), "r"(a3), "r"(b0), "r"(b1));
}
#define F2U(x) __float_as_uint(x)

// projection outputs (device-global scratch).
// g_Q, g_K: [b,s,h] with h permuted within each 8-block (order 0,4,1,5,2,6,3,7)
// g_V:      [b,h,s] (transposed) with s permuted within each 8-block
__device__ float g_Q[NB*SEQ*HID];
__device__ float g_K[NB*SEQ*HID];
__device__ float g_V[NB*SEQ*HID];

// ============================================================================
// Projection via tf32 mma.sync: Y = X @ W. CTA tile 128m x 128n, 256 threads,
// 8 warps (4 rg x 2 cg), warp tile 32x64. Epilogue writes the pair-permuted
// (and for V, transposed) layouts consumed by the attention kernel.
// smem: Ws[128][260] | As 2x[128][36]
// ============================================================================
#define PWSTR 260
#define PASTR 36
#define P_OFF_A 33280
#define P_ASLOT 4608
#define P_SMEM ((33280 + 2*4608) * 4)

__global__ void __launch_bounds__(256, 1)
proj_kernel(const float* __restrict__ q, const float* __restrict__ k, const float* __restrict__ v,
            const float* __restrict__ Wq, const float* __restrict__ Wk, const float* __restrict__ Wv)
{
    extern __shared__ float psm[];
    float* Ws = psm;
    float* As = psm + P_OFF_A;
    const uint32_t sA = smem_u32(As);

    const float* X; const float* W; float* Y;
    if (blockIdx.z == 0)      { X = q; W = Wq; Y = g_Q; }
    else if (blockIdx.z == 1) { X = k; W = Wk; Y = g_K; }
    else                      { X = v; W = Wv; Y = g_V; }
    const bool isV = (blockIdx.z == 2);

    const int tid = threadIdx.x;
    const int wid = tid >> 5, lane = tid & 31;
    const int rg = wid >> 1, cg = wid & 1;
    const int r0 = rg * 32, c0 = cg * 64;
    const int g = lane >> 2, tg = lane & 3;
    const int m0 = blockIdx.y * 128;
    const int n0 = blockIdx.x * 128;

    // issue A chunk 0 (slot 0)
    #pragma unroll
    for (int p = 0; p < 4; p++){
        int flat = tid + 256*p;
        int r = flat >> 3, j = flat & 7;
        CPASYNC16(sA + (r*PASTR + j*4)*4, (const void*)&X[(size_t)(m0 + r)*HID + j*4]);
    }
    CP_COMMIT();

    // W transpose into Ws[n][k], RN-rounded to tf32 (coalesced LDG rows)
    {
        const int n = (wid & 3)*32 + lane;
        const int kq0 = wid >> 2;
        #pragma unroll 4
        for (int i = 0; i < 32; i++){
            int kq = kq0 + 2*i;
            float a0 = W[(size_t)(kq*4+0)*HID + n0 + n];
            float a1 = W[(size_t)(kq*4+1)*HID + n0 + n];
            float a2 = W[(size_t)(kq*4+2)*HID + n0 + n];
            float a3 = W[(size_t)(kq*4+3)*HID + n0 + n];
            *(float4*)&Ws[n*PWSTR + kq*4] =
                make_float4(tf32r(a0), tf32r(a1), tf32r(a2), tf32r(a3));
        }
    }

    float acc[2][8][4];
    #pragma unroll
    for (int mi = 0; mi < 2; mi++)
        #pragma unroll
        for (int nt = 0; nt < 8; nt++)
            #pragma unroll
            for (int j = 0; j < 4; j++) acc[mi][nt][j] = 0.f;

    #pragma unroll 1
    for (int kc = 0; kc < 8; kc++){
        CP_WAIT(0);
        __syncthreads();           // publishes chunk kc (and Ws on kc==0)
        if (kc < 7){
            const uint32_t dst = sA + (((kc+1)&1)*P_ASLOT)*4;
            #pragma unroll
            for (int p = 0; p < 4; p++){
                int flat = tid + 256*p;
                int r = flat >> 3, j = flat & 7;
                CPASYNC16(dst + (r*PASTR + j*4)*4,
                          (const void*)&X[(size_t)(m0 + r)*HID + (kc+1)*32 + j*4]);
            }
            CP_COMMIT();
        }
        const float* Ab = As + (kc&1)*P_ASLOT;
        #pragma unroll
        for (int ks = 0; ks < 4; ks++){
            int kk = ks*8;
            uint32_t a[2][4];
            #pragma unroll
            for (int mi = 0; mi < 2; mi++){
                int base = (r0 + 16*mi + g)*PASTR + kk + tg;
                a[mi][0] = tf32u(Ab[base]);
                a[mi][1] = tf32u(Ab[base + 8*PASTR]);
                a[mi][2] = tf32u(Ab[base + 4]);
                a[mi][3] = tf32u(Ab[base + 8*PASTR + 4]);
            }
            #pragma unroll
            for (int nt = 0; nt < 8; nt++){
                int c = c0 + nt*8 + g;
                uint32_t b0 = F2U(Ws[c*PWSTR + kc*32 + kk + tg]);
                uint32_t b1 = F2U(Ws[c*PWSTR + kc*32 + kk + tg + 4]);
                mma8(acc[0][nt], a[0][0], a[0][1], a[0][2], a[0][3], b0, b1);
                mma8(acc[1][nt], a[1][0], a[1][1], a[1][2], a[1][3], b0, b1);
            }
        }
    }

    // ---- epilogue: tf32-RN round + permuted layouts for attention ----
    // within-8 position map: pos(j) = 2j (j<4) else 2(j-4)+1
    const int pA = (tg < 2) ? 4*tg : 4*tg - 7;   // pos(2tg)
    const int pB = pA + 2;                       // pos(2tg+1)
    const int pg = (g < 4) ? 2*g : 2*(g-4) + 1;  // pos(g) for V s-permutation
    #pragma unroll
    for (int mi = 0; mi < 2; mi++){
        int row = m0 + r0 + 16*mi + g;           // global m (b*2048 + s)
        #pragma unroll
        for (int nt = 0; nt < 8; nt++){
            int colb = n0 + c0 + nt*8;
            float v00 = tf32r(acc[mi][nt][0]);   // (row,   n=colb+2tg)
            float v01 = tf32r(acc[mi][nt][1]);   // (row,   n=colb+2tg+1)
            float v10 = tf32r(acc[mi][nt][2]);   // (row+8, n=colb+2tg)
            float v11 = tf32r(acc[mi][nt][3]);   // (row+8, n=colb+2tg+1)
            if (!isV){
                Y[(size_t)row*HID + colb + pA]     = v00;
                Y[(size_t)row*HID + colb + pB]     = v01;
                Y[(size_t)(row+8)*HID + colb + pA] = v10;
                Y[(size_t)(row+8)*HID + colb + pB] = v11;
            } else {
                size_t bb = (size_t)(row >> 11) * (SEQ*HID);
                int sblk = (row & 2047) & ~7;    // row&7 == g
                Y[bb + (size_t)(colb+2*tg  )*SEQ + sblk + pg]     = v00;
                Y[bb + (size_t)(colb+2*tg+1)*SEQ + sblk + pg]     = v01;
                Y[bb + (size_t)(colb+2*tg  )*SEQ + sblk + 8 + pg] = v10;
                Y[bb + (size_t)(colb+2*tg+1)*SEQ + sblk + 8 + pg] = v11;
            }
        }
    }
}

// ============================================================================
// Flash attention via mma.sync tf32 — 512 threads, 16 warps (4 rg x 4 cq).
// Pair-permuted layouts -> all fragment loads are LDS.64 (half the LDS issue).
// K/V chunk tiles [256][32], XOR swizzle (e ^ 8*(row&3)), 2 slots, 1 sync/chunk.
// No-max softmax (|S|<=~2); P tf32-rounded and s-permuted at write.
// smem (floats): Qs[64][264] | Ps[64][264] | KV 2x8192 | lp[64][4]
// ============================================================================
#define QSTR 264
#define O_PS 16896
#define O_KV 33792
#define KVSLOT 8192
#define O_LP 50176
#define SMEM_ATTN (50432 * 4)

__global__ void __launch_bounds__(512, 1)
attn_kernel(const uint32_t* __restrict__ mask, float* __restrict__ out)
{
    extern __shared__ float sm[];
    float* Qs = sm;
    float* Ps = sm + O_PS;
    float* KV = sm + O_KV;
    float* lp = sm + O_LP;
    const uint32_t sQ  = smem_u32(Qs);
    const uint32_t sKV = smem_u32(KV);

    const int tid  = threadIdx.x;
    const int wid  = tid >> 5, lane = tid & 31;
    const int rg   = wid >> 2, cq = wid & 3;
    const int r0   = rg * 16;
    const int c0   = cq * 64;
    const int g    = lane >> 2, tg = lane & 3;
    const int b    = blockIdx.y;
    const int q0   = blockIdx.x * BM;
    const int m8   = 8*(g & 3);          // XOR-swizzle key for K/V rows (row&3 == g&3)

    const float* Qg = g_Q + (size_t)b*SEQ*HID;
    const float* Kg = g_K + (size_t)b*SEQ*HID;
    const float* Vg = g_V + (size_t)b*SEQ*HID;   // [h][s] layout
    const uint32_t* Mg = mask + (size_t)b*SEQ*SEQ;

    // ---- load Q tile [64][256] -> Qs[64][264] (already h-pair-permuted) ----
    #pragma unroll
    for (int p = 0; p < 8; p++){
        int idx = tid + 512*p;
        int r = idx >> 6, j = idx & 63;
        CPASYNC16(sQ + (r*QSTR + j*4)*4, (const void*)&Qg[(size_t)(q0 + r)*HID + j*4]);
    }
    CP_COMMIT();

    float oacc[8][4];
    #pragma unroll
    for (int i = 0; i < 8; i++)
        #pragma unroll
        for (int j = 0; j < 4; j++) oacc[i][j] = 0.f;
    float lsum0 = 0.f, lsum1 = 0.f;

    CP_WAIT(0);
    __syncthreads();

    for (int t = 0; t < SEQ/BN; t++){
        const int k0 = t * BN;

        // ===== QK^T: 8 hid-chunks of 32, 2 slots, ONE sync per chunk =====
        float sacc[8][4];
        #pragma unroll
        for (int i = 0; i < 8; i++)
            #pragma unroll
            for (int j = 0; j < 4; j++) sacc[i][j] = 0.f;

        // preamble: K chunk 0 -> slot 0 ([c=256][32], XOR-swizzled)
        #pragma unroll
        for (int p = 0; p < 4; p++){
            int flat = tid + 512*p;
            int c = flat >> 3, j = flat & 7;
            CPASYNC16(sKV + (c*32 + ((4*j) ^ (8*(c&3))))*4,
                      (const void*)&Kg[(size_t)(k0 + c)*HID + 4*j]);
        }
        CP_COMMIT();

        #pragma unroll 1
        for (int hc = 0; hc < 8; hc++){
            CP_WAIT(0);
            __syncthreads();
            if (hc < 7){
                const uint32_t dst = sKV + (((hc+1)&1)*KVSLOT)*4;
                #pragma unroll
                for (int p = 0; p < 4; p++){
                    int flat = tid + 512*p;
                    int c = flat >> 3, j = flat & 7;
                    CPASYNC16(dst + (c*32 + ((4*j) ^ (8*(c&3))))*4,
                              (const void*)&Kg[(size_t)(k0 + c)*HID + (hc+1)*32 + 4*j]);
                }
                CP_COMMIT();
            }
            const float* Kb = KV + (hc&1)*KVSLOT;
            #pragma unroll
            for (int ks = 0; ks < 4; ks++){
                int kk = ks*8;
                int hb = hc*32 + kk;
                float2 aA = *(const float2*)&Qs[(r0+g  )*QSTR + hb + 2*tg];
                float2 aB = *(const float2*)&Qs[(r0+g+8)*QSTR + hb + 2*tg];
                uint32_t a0 = F2U(aA.x), a2 = F2U(aA.y);
                uint32_t a1 = F2U(aB.x), a3 = F2U(aB.y);
                int koff = (kk ^ m8) + 2*tg;
                #pragma unroll
                for (int nt = 0; nt < 8; nt++){
                    int c = c0 + nt*8 + g;
                    float2 bb = *(const float2*)&Kb[c*32 + koff];
                    mma8(sacc[nt], a0, a1, a2, a3, F2U(bb.x), F2U(bb.y));
                }
            }
        }

        // V chunk 0 -> slot 0 (Vt [h=256][32], XOR-swizzled)
        #pragma unroll
        for (int p = 0; p < 4; p++){
            int flat = tid + 512*p;
            int h = flat >> 3, j = flat & 7;
            CPASYNC16(sKV + (h*32 + ((4*j) ^ (8*(h&3))))*4,
                      (const void*)&Vg[(size_t)h*SEQ + k0 + 4*j]);
        }
        CP_COMMIT();

        // ===== softmax (no max): P = mask ? 0 : tf32(exp(S/16)), s-permuted =====
        {
            const uint32_t* mr0 = Mg + (size_t)(q0 + r0 + g)*SEQ + k0 + c0 + 2*tg;
            const uint32_t* mr1 = mr0 + 8*SEQ;
            const int pA = (tg < 2) ? 4*tg : 4*tg - 7;
            #pragma unroll
            for (int nt = 0; nt < 8; nt++){
                uint2 m0v = *(const uint2*)(mr0 + nt*8);
                uint2 m1v = *(const uint2*)(mr1 + nt*8);
                float p00 = m0v.x ? 0.f : tf32r(__expf(sacc[nt][0] * QKSCALE));
                float p01 = m0v.y ? 0.f : tf32r(__expf(sacc[nt][1] * QKSCALE));
                float p10 = m1v.x ? 0.f : tf32r(__expf(sacc[nt][2] * QKSCALE));
                float p11 = m1v.y ? 0.f : tf32r(__expf(sacc[nt][3] * QKSCALE));
                lsum0 += p00 + p01;
                lsum1 += p10 + p11;
                int colb = c0 + nt*8;
                Ps[(r0+g  )*QSTR + colb + pA]     = p00;
                Ps[(r0+g  )*QSTR + colb + pA + 2] = p01;
                Ps[(r0+g+8)*QSTR + colb + pA]     = p10;
                Ps[(r0+g+8)*QSTR + colb + pA + 2] = p11;
            }
        }

        // ===== P @ V: 8 s-chunks of 32, 2 slots, ONE sync per chunk =====
        #pragma unroll 1
        for (int cc = 0; cc < 8; cc++){
            CP_WAIT(0);
            __syncthreads();       // V chunk cc visible; Ps published (cc==0)
            if (cc < 7){
                const uint32_t dst = sKV + (((cc+1)&1)*KVSLOT)*4;
                #pragma unroll
                for (int p = 0; p < 4; p++){
                    int flat = tid + 512*p;
                    int h = flat >> 3, j = flat & 7;
                    CPASYNC16(dst + (h*32 + ((4*j) ^ (8*(h&3))))*4,
                              (const void*)&Vg[(size_t)h*SEQ + k0 + (cc+1)*32 + 4*j]);
                }
                CP_COMMIT();
            }
            const float* Vb = KV + (cc&1)*KVSLOT;
            #pragma unroll
            for (int ks = 0; ks < 4; ks++){
                int kk = ks*8;
                int cb = cc*32 + kk;
                float2 pAf = *(const float2*)&Ps[(r0+g  )*QSTR + cb + 2*tg];
                float2 pBf = *(const float2*)&Ps[(r0+g+8)*QSTR + cb + 2*tg];
                uint32_t a0 = F2U(pAf.x), a2 = F2U(pAf.y);
                uint32_t a1 = F2U(pBf.x), a3 = F2U(pBf.y);
                int koff = (kk ^ m8) + 2*tg;
                #pragma unroll
                for (int nt = 0; nt < 8; nt++){
                    int h = c0 + nt*8 + g;
                    float2 vv = *(const float2*)&Vb[h*32 + koff];
                    mma8(oacc[nt], a0, a1, a2, a3, F2U(vv.x), F2U(vv.y));
                }
            }
        }
    }

    // ===== epilogue: l reduce + O /= l (fully-masked rows -> 0) =====
    lsum0 += __shfl_xor_sync(0xffffffffu, lsum0, 1);
    lsum0 += __shfl_xor_sync(0xffffffffu, lsum0, 2);
    lsum1 += __shfl_xor_sync(0xffffffffu, lsum1, 1);
    lsum1 += __shfl_xor_sync(0xffffffffu, lsum1, 2);
    if (tg == 0){
        lp[(r0+g  )*4 + cq] = lsum0;
        lp[(r0+g+8)*4 + cq] = lsum1;
    }
    __syncthreads();
    float l0 = lp[(r0+g  )*4] + lp[(r0+g  )*4 + 1] + lp[(r0+g  )*4 + 2] + lp[(r0+g  )*4 + 3];
    float l1 = lp[(r0+g+8)*4] + lp[(r0+g+8)*4 + 1] + lp[(r0+g+8)*4 + 2] + lp[(r0+g+8)*4 + 3];
    float inv0 = (l0 > 0.f) ? (1.f/l0) : 0.f;
    float inv1 = (l1 > 0.f) ? (1.f/l1) : 0.f;

    float* or0 = out + (size_t)(b*SEQ + q0 + r0 + g)*HID;
    float* or1 = or0 + 8*HID;
    #pragma unroll
    for (int nt = 0; nt < 8; nt++){
        int h = c0 + nt*8 + 2*tg;           // O columns are natural h (V h unpermuted)
        *(float2*)&or0[h] = make_float2(oacc[nt][0]*inv0, oacc[nt][1]*inv0);
        *(float2*)&or1[h] = make_float2(oacc[nt][2]*inv1, oacc[nt][3]*inv1);
    }
}

// ============================================================================
extern "C" void kernel_launch(void* const* d_in, const int* in_sizes, int n_in,
                              void* d_out, int out_size)
{
    (void)in_sizes; (void)n_in; (void)out_size;
    const float* k  = (const float*)d_in[0];
    const float* q  = (const float*)d_in[1];
    const float* v  = (const float*)d_in[2];
    const uint32_t* mask = (const uint32_t*)d_in[3];
    const float* Wq = (const float*)d_in[4];
    const float* Wk = (const float*)d_in[5];
    const float* Wv = (const float*)d_in[6];
    float* out = (float*)d_out;

    cudaFuncSetAttribute(proj_kernel,
                         cudaFuncAttributeMaxDynamicSharedMemorySize, P_SMEM);
    proj_kernel<<<dim3(2, 128, 3), 256, P_SMEM>>>(q, k, v, Wq, Wk, Wv);

    cudaFuncSetAttribute(attn_kernel,
                         cudaFuncAttributeMaxDynamicSharedMemorySize, SMEM_ATTN);
    attn_kernel<<<dim3(SEQ/BM, NB), 512, SMEM_ATTN>>>(mask, out);
}

// round 13
// speedup vs baseline: 1.0822x; 1.0822x over previous
#include <cuda_runtime.h>
#include <cstdint>

#define NB  8
#define SEQ 2048
#define HID 256
#define BM  32
#define BN  256
#define QKSCALE 0.0625f

typedef unsigned long long ull;

__device__ __forceinline__ uint32_t smem_u32(const void* p){
    uint32_t a;
    asm("{ .reg .u64 t; cvta.to.shared.u64 t, %1; cvt.u32.u64 %0, t; }" : "=r"(a) : "l"(p));
    return a;
}
// round fp32 -> tf32 (RN, unbiased)
__device__ __forceinline__ float tf32r(float x){
    uint32_t u; asm("cvt.rna.tf32.f32 %0, %1;" : "=r"(u) : "f"(x));
    return __uint_as_float(u);
}
__device__ __forceinline__ uint32_t tf32u(float x){
    uint32_t u; asm("cvt.rna.tf32.f32 %0, %1;" : "=r"(u) : "f"(x));
    return u;
}
#define CPASYNC16(dst, src) \
    asm volatile("cp.async.cg.shared.global [%0], [%1], 16;" :: "r"(dst), "l"(src) : "memory")
#define CP_COMMIT()  asm volatile("cp.async.commit_group;" ::: "memory")
#define CP_WAIT(n)   asm volatile("cp.async.wait_group %0;" :: "n"(n) : "memory")

// m16n8k8 tf32 mma
__device__ __forceinline__ void mma8(float* c,
    uint32_t a0, uint32_t a1, uint32_t a2, uint32_t a3, uint32_t b0, uint32_t b1)
{
    asm volatile("mma.sync.aligned.m16n8k8.row.col.f32.tf32.tf32.f32 "
        "{%0,%1,%2,%3}, {%4,%5,%6,%7}, {%8,%9}, {%0,%1,%2,%3};"
        : "+f"(c[0]), "+f"(c[1]), "+f"(c[2]), "+f"(c[3])
        : "r"(a0), "r"(a1), "r"(a2), "r"(a3), "r"(b0), "r"(b1));
}
#define F2U(x) __float_as_uint(x)

// projection outputs (device-global scratch, natural [b,s,h] layouts)
__device__ float g_Q[NB*SEQ*HID];
__device__ float g_K[NB*SEQ*HID];
__device__ float g_V[NB*SEQ*HID];

// ============================================================================
// Projection via tf32 mma.sync: Y = X @ W. CTA tile 128m x 128n, 256 threads,
// 8 warps (4 rg x 2 cg), warp tile 32x64. W transposed once into smem and
// RN-rounded to tf32 there; A fragments RN-rounded at register load.
// smem: Ws[128][260] | As 2x[128][36]       (round-11 version, 63us, verbatim)
// ============================================================================
#define PWSTR 260
#define PASTR 36
#define P_OFF_A 33280
#define P_ASLOT 4608
#define P_SMEM ((33280 + 2*4608) * 4)

__global__ void __launch_bounds__(256, 1)
proj_kernel(const float* __restrict__ q, const float* __restrict__ k, const float* __restrict__ v,
            const float* __restrict__ Wq, const float* __restrict__ Wk, const float* __restrict__ Wv)
{
    extern __shared__ float psm[];
    float* Ws = psm;
    float* As = psm + P_OFF_A;
    const uint32_t sA = smem_u32(As);

    const float* X; const float* W; float* Y;
    if (blockIdx.z == 0)      { X = q; W = Wq; Y = g_Q; }
    else if (blockIdx.z == 1) { X = k; W = Wk; Y = g_K; }
    else                      { X = v; W = Wv; Y = g_V; }

    const int tid = threadIdx.x;
    const int wid = tid >> 5, lane = tid & 31;
    const int rg = wid >> 1, cg = wid & 1;
    const int r0 = rg * 32, c0 = cg * 64;
    const int g = lane >> 2, tg = lane & 3;
    const int m0 = blockIdx.y * 128;
    const int n0 = blockIdx.x * 128;

    // issue A chunk 0 (slot 0)
    #pragma unroll
    for (int p = 0; p < 4; p++){
        int flat = tid + 256*p;
        int r = flat >> 3, j = flat & 7;
        CPASYNC16(sA + (r*PASTR + j*4)*4, (const void*)&X[(size_t)(m0 + r)*HID + j*4]);
    }
    CP_COMMIT();

    // W transpose into Ws[n][k], RN-rounded to tf32 (coalesced LDG rows)
    {
        const int n = (wid & 3)*32 + lane;
        const int kq0 = wid >> 2;
        #pragma unroll 4
        for (int i = 0; i < 32; i++){
            int kq = kq0 + 2*i;
            float a0 = W[(size_t)(kq*4+0)*HID + n0 + n];
            float a1 = W[(size_t)(kq*4+1)*HID + n0 + n];
            float a2 = W[(size_t)(kq*4+2)*HID + n0 + n];
            float a3 = W[(size_t)(kq*4+3)*HID + n0 + n];
            *(float4*)&Ws[n*PWSTR + kq*4] =
                make_float4(tf32r(a0), tf32r(a1), tf32r(a2), tf32r(a3));
        }
    }

    float acc[2][8][4];
    #pragma unroll
    for (int mi = 0; mi < 2; mi++)
        #pragma unroll
        for (int nt = 0; nt < 8; nt++)
            #pragma unroll
            for (int j = 0; j < 4; j++) acc[mi][nt][j] = 0.f;

    #pragma unroll 1
    for (int kc = 0; kc < 8; kc++){
        CP_WAIT(0);
        __syncthreads();           // publishes chunk kc (and Ws on kc==0)
        if (kc < 7){
            const uint32_t dst = sA + (((kc+1)&1)*P_ASLOT)*4;
            #pragma unroll
            for (int p = 0; p < 4; p++){
                int flat = tid + 256*p;
                int r = flat >> 3, j = flat & 7;
                CPASYNC16(dst + (r*PASTR + j*4)*4,
                          (const void*)&X[(size_t)(m0 + r)*HID + (kc+1)*32 + j*4]);
            }
            CP_COMMIT();
        }
        const float* Ab = As + (kc&1)*P_ASLOT;
        #pragma unroll
        for (int ks = 0; ks < 4; ks++){
            int kk = ks*8;
            uint32_t a[2][4];
            #pragma unroll
            for (int mi = 0; mi < 2; mi++){
                int base = (r0 + 16*mi + g)*PASTR + kk + tg;
                a[mi][0] = tf32u(Ab[base]);
                a[mi][1] = tf32u(Ab[base + 8*PASTR]);
                a[mi][2] = tf32u(Ab[base + 4]);
                a[mi][3] = tf32u(Ab[base + 8*PASTR + 4]);
            }
            #pragma unroll
            for (int nt = 0; nt < 8; nt++){
                int c = c0 + nt*8 + g;
                uint32_t b0 = F2U(Ws[c*PWSTR + kc*32 + kk + tg]);      // already tf32
                uint32_t b1 = F2U(Ws[c*PWSTR + kc*32 + kk + tg + 4]);
                mma8(acc[0][nt], a[0][0], a[0][1], a[0][2], a[0][3], b0, b1);
                mma8(acc[1][nt], a[1][0], a[1][1], a[1][2], a[1][3], b0, b1);
            }
        }
    }

    // epilogue: round to tf32 (RN) for the attention MMAs
    #pragma unroll
    for (int mi = 0; mi < 2; mi++){
        int row = m0 + r0 + 16*mi + g;
        #pragma unroll
        for (int nt = 0; nt < 8; nt++){
            int col = n0 + c0 + nt*8 + 2*tg;
            *(float2*)&Y[(size_t)row*HID + col] =
                make_float2(tf32r(acc[mi][nt][0]), tf32r(acc[mi][nt][1]));
            *(float2*)&Y[(size_t)(row+8)*HID + col] =
                make_float2(tf32r(acc[mi][nt][2]), tf32r(acc[mi][nt][3]));
        }
    }
}

// ============================================================================
// Flash attention via mma.sync tf32 — BM=32, 256 threads, 8 warps (2 rg x 4 cq),
// TWO CTAs per SM (smem 105.5KB) so barriers of one CTA overlap compute of the
// other. K chunks of 16 ([256][20]), V chunks of 16 ([16][264]), 2 slots,
// ONE sync per chunk. No-max softmax; P tf32-rounded (round-9/11 numerics).
// smem (floats): Qs[32][260] | Ps[32][260] | KV 2x5120 | lp[32][4]
// ============================================================================
#define QSTR 260
#define KSTR 20
#define VSTR 264
#define O_PS 8320
#define O_KV 16640
#define KVSLOT 5120
#define O_LP 26880
#define SMEM_ATTN (27008 * 4)

__global__ void __launch_bounds__(256, 2)
attn_kernel(const uint32_t* __restrict__ mask, float* __restrict__ out)
{
    extern __shared__ float sm[];
    float* Qs = sm;
    float* Ps = sm + O_PS;
    float* KV = sm + O_KV;
    float* lp = sm + O_LP;
    const uint32_t sQ  = smem_u32(Qs);
    const uint32_t sKV = smem_u32(KV);

    const int tid  = threadIdx.x;
    const int wid  = tid >> 5, lane = tid & 31;
    const int rg   = wid >> 2, cq = wid & 3;
    const int r0   = rg * 16;
    const int c0   = cq * 64;
    const int g    = lane >> 2, tg = lane & 3;
    const int b    = blockIdx.y;
    const int q0   = blockIdx.x * BM;

    const float* Qg = g_Q + (size_t)b*SEQ*HID;
    const float* Kg = g_K + (size_t)b*SEQ*HID;
    const float* Vg = g_V + (size_t)b*SEQ*HID;
    const uint32_t* Mg = mask + (size_t)b*SEQ*SEQ;

    // ---- load Q tile [32][256] -> Qs[32][260] ----
    #pragma unroll
    for (int p = 0; p < 8; p++){
        int idx = tid + 256*p;
        int r = idx >> 6, j = idx & 63;
        CPASYNC16(sQ + (r*QSTR + j*4)*4, (const void*)&Qg[(size_t)(q0 + r)*HID + j*4]);
    }
    CP_COMMIT();

    float oacc[8][4];
    #pragma unroll
    for (int i = 0; i < 8; i++)
        #pragma unroll
        for (int j = 0; j < 4; j++) oacc[i][j] = 0.f;
    float lsum0 = 0.f, lsum1 = 0.f;

    CP_WAIT(0);
    __syncthreads();

    for (int t = 0; t < SEQ/BN; t++){
        const int k0 = t * BN;

        // ===== QK^T: 16 hid-chunks of 16, 2 slots, ONE sync per chunk =====
        float sacc[8][4];
        #pragma unroll
        for (int i = 0; i < 8; i++)
            #pragma unroll
            for (int j = 0; j < 4; j++) sacc[i][j] = 0.f;

        // preamble: K chunk 0 -> slot 0
        #pragma unroll
        for (int p = 0; p < 4; p++){
            int flat = tid + 256*p;
            int c = flat >> 2, j = flat & 3;
            CPASYNC16(sKV + (c*KSTR + j*4)*4, (const void*)&Kg[(size_t)(k0 + c)*HID + j*4]);
        }
        CP_COMMIT();

        #pragma unroll 1
        for (int hc = 0; hc < 16; hc++){
            CP_WAIT(0);
            __syncthreads();       // chunk hc visible; everyone past compute hc-1
            if (hc < 15){
                const uint32_t dst = sKV + (((hc+1)&1)*KVSLOT)*4;
                #pragma unroll
                for (int p = 0; p < 4; p++){
                    int flat = tid + 256*p;
                    int c = flat >> 2, j = flat & 3;
                    CPASYNC16(dst + (c*KSTR + j*4)*4,
                              (const void*)&Kg[(size_t)(k0 + c)*HID + (hc+1)*16 + j*4]);
                }
                CP_COMMIT();
            }
            const float* Kb = KV + (hc&1)*KVSLOT;
            #pragma unroll
            for (int ks = 0; ks < 2; ks++){
                int kk = ks*8;
                int hb = hc*16 + kk;
                uint32_t a0 = F2U(Qs[(r0+g  )*QSTR + hb + tg]);
                uint32_t a1 = F2U(Qs[(r0+g+8)*QSTR + hb + tg]);
                uint32_t a2 = F2U(Qs[(r0+g  )*QSTR + hb + tg + 4]);
                uint32_t a3 = F2U(Qs[(r0+g+8)*QSTR + hb + tg + 4]);
                #pragma unroll
                for (int nt = 0; nt < 8; nt++){
                    int c = c0 + nt*8 + g;
                    uint32_t b0 = F2U(Kb[c*KSTR + kk + tg]);
                    uint32_t b1 = F2U(Kb[c*KSTR + kk + tg + 4]);
                    mma8(sacc[nt], a0, a1, a2, a3, b0, b1);
                }
            }
        }

        // V chunk 0 -> slot 0 (slot held K chunk 14; all warps past hc=15 sync)
        #pragma unroll
        for (int p = 0; p < 4; p++){
            int flat = tid + 256*p;
            int c = flat >> 6, j = flat & 63;
            CPASYNC16(sKV + (c*VSTR + j*4)*4, (const void*)&Vg[(size_t)(k0 + c)*HID + j*4]);
        }
        CP_COMMIT();

        // ===== softmax (no max): P = mask ? 0 : tf32(exp(S/16)) =====
        {
            const uint32_t* mr0 = Mg + (size_t)(q0 + r0 + g)*SEQ + k0 + c0 + 2*tg;
            const uint32_t* mr1 = mr0 + 8*SEQ;
            #pragma unroll
            for (int nt = 0; nt < 8; nt++){
                uint2 m0v = *(const uint2*)(mr0 + nt*8);
                uint2 m1v = *(const uint2*)(mr1 + nt*8);
                float p00 = m0v.x ? 0.f : tf32r(__expf(sacc[nt][0] * QKSCALE));
                float p01 = m0v.y ? 0.f : tf32r(__expf(sacc[nt][1] * QKSCALE));
                float p10 = m1v.x ? 0.f : tf32r(__expf(sacc[nt][2] * QKSCALE));
                float p11 = m1v.y ? 0.f : tf32r(__expf(sacc[nt][3] * QKSCALE));
                lsum0 += p00 + p01;
                lsum1 += p10 + p11;
                int col = c0 + nt*8 + 2*tg;
                *(float2*)&Ps[(r0+g  )*QSTR + col] = make_float2(p00, p01);
                *(float2*)&Ps[(r0+g+8)*QSTR + col] = make_float2(p10, p11);
            }
        }

        // ===== P @ V: 16 c-chunks of 16, 2 slots, ONE sync per chunk =====
        #pragma unroll 1
        for (int cc = 0; cc < 16; cc++){
            CP_WAIT(0);
            __syncthreads();       // V chunk cc visible; Ps published (cc==0)
            if (cc < 15){
                const uint32_t dst = sKV + (((cc+1)&1)*KVSLOT)*4;
                #pragma unroll
                for (int p = 0; p < 4; p++){
                    int flat = tid + 256*p;
                    int c = flat >> 6, j = flat & 63;
                    CPASYNC16(dst + (c*VSTR + j*4)*4,
                              (const void*)&Vg[(size_t)(k0 + (cc+1)*16 + c)*HID + j*4]);
                }
                CP_COMMIT();
            }
            const float* Vb = KV + (cc&1)*KVSLOT;
            #pragma unroll
            for (int ks = 0; ks < 2; ks++){
                int kk = ks*8;
                int cb = cc*16 + kk;
                uint32_t a0 = F2U(Ps[(r0+g  )*QSTR + cb + tg]);
                uint32_t a1 = F2U(Ps[(r0+g+8)*QSTR + cb + tg]);
                uint32_t a2 = F2U(Ps[(r0+g  )*QSTR + cb + tg + 4]);
                uint32_t a3 = F2U(Ps[(r0+g+8)*QSTR + cb + tg + 4]);
                const float* Vb0 = Vb + (kk + tg)*VSTR;
                const float* Vb1 = Vb + (kk + tg + 4)*VSTR;
                #pragma unroll
                for (int nt = 0; nt < 8; nt++){
                    int h = c0 + nt*8 + g;
                    uint32_t b0 = F2U(Vb0[h]);
                    uint32_t b1 = F2U(Vb1[h]);
                    mma8(oacc[nt], a0, a1, a2, a3, b0, b1);
                }
            }
        }
    }

    // ===== epilogue: l reduce + O /= l (fully-masked rows -> 0) =====
    lsum0 += __shfl_xor_sync(0xffffffffu, lsum0, 1);
    lsum0 += __shfl_xor_sync(0xffffffffu, lsum0, 2);
    lsum1 += __shfl_xor_sync(0xffffffffu, lsum1, 1);
    lsum1 += __shfl_xor_sync(0xffffffffu, lsum1, 2);
    if (tg == 0){
        lp[(r0+g  )*4 + cq] = lsum0;
        lp[(r0+g+8)*4 + cq] = lsum1;
    }
    __syncthreads();
    float l0 = lp[(r0+g  )*4] + lp[(r0+g  )*4 + 1] + lp[(r0+g  )*4 + 2] + lp[(r0+g  )*4 + 3];
    float l1 = lp[(r0+g+8)*4] + lp[(r0+g+8)*4 + 1] + lp[(r0+g+8)*4 + 2] + lp[(r0+g+8)*4 + 3];
    float inv0 = (l0 > 0.f) ? (1.f/l0) : 0.f;
    float inv1 = (l1 > 0.f) ? (1.f/l1) : 0.f;

    float* or0 = out + (size_t)(b*SEQ + q0 + r0 + g)*HID;
    float* or1 = or0 + 8*HID;
    #pragma unroll
    for (int nt = 0; nt < 8; nt++){
        int h = c0 + nt*8 + 2*tg;
        *(float2*)&or0[h] = make_float2(oacc[nt][0]*inv0, oacc[nt][1]*inv0);
        *(float2*)&or1[h] = make_float2(oacc[nt][2]*inv1, oacc[nt][3]*inv1);
    }
}

// ============================================================================
extern "C" void kernel_launch(void* const* d_in, const int* in_sizes, int n_in,
                              void* d_out, int out_size)
{
    (void)in_sizes; (void)n_in; (void)out_size;
    const float* k  = (const float*)d_in[0];
    const float* q  = (const float*)d_in[1];
    const float* v  = (const float*)d_in[2];
    const uint32_t* mask = (const uint32_t*)d_in[3];
    const float* Wq = (const float*)d_in[4];
    const float* Wk = (const float*)d_in[5];
    const float* Wv = (const float*)d_in[6];
    float* out = (float*)d_out;

    cudaFuncSetAttribute(proj_kernel,
                         cudaFuncAttributeMaxDynamicSharedMemorySize, P_SMEM);
    proj_kernel<<<dim3(2, 128, 3), 256, P_SMEM>>>(q, k, v, Wq, Wk, Wv);

    cudaFuncSetAttribute(attn_kernel,
                         cudaFuncAttributeMaxDynamicSharedMemorySize, SMEM_ATTN);
    attn_kernel<<<dim3(SEQ/BM, NB), 256, SMEM_ATTN>>>(mask, out);
}

// round 14
// speedup vs baseline: 1.3838x; 1.2787x over previous
#include <cuda_runtime.h>
#include <cstdint>

#define NB  8
#define SEQ 2048
#define HID 256
#define BM  64
#define BN  256
#define QKSCALE 0.0625f

typedef unsigned long long ull;

__device__ __forceinline__ uint32_t smem_u32(const void* p){
    uint32_t a;
    asm("{ .reg .u64 t; cvta.to.shared.u64 t, %1; cvt.u32.u64 %0, t; }" : "=r"(a) : "l"(p));
    return a;
}
// round fp32 -> tf32 (RN, unbiased)
__device__ __forceinline__ float tf32r(float x){
    uint32_t u; asm("cvt.rna.tf32.f32 %0, %1;" : "=r"(u) : "f"(x));
    return __uint_as_float(u);
}
__device__ __forceinline__ uint32_t tf32u(float x){
    uint32_t u; asm("cvt.rna.tf32.f32 %0, %1;" : "=r"(u) : "f"(x));
    return u;
}
#define CPASYNC16(dst, src) \
    asm volatile("cp.async.cg.shared.global [%0], [%1], 16;" :: "r"(dst), "l"(src) : "memory")
#define CP_COMMIT()  asm volatile("cp.async.commit_group;" ::: "memory")
#define CP_WAIT(n)   asm volatile("cp.async.wait_group %0;" :: "n"(n) : "memory")

// m16n8k8 tf32 mma
__device__ __forceinline__ void mma8(float* c,
    uint32_t a0, uint32_t a1, uint32_t a2, uint32_t a3, uint32_t b0, uint32_t b1)
{
    asm volatile("mma.sync.aligned.m16n8k8.row.col.f32.tf32.tf32.f32 "
        "{%0,%1,%2,%3}, {%4,%5,%6,%7}, {%8,%9}, {%0,%1,%2,%3};"
        : "+f"(c[0]), "+f"(c[1]), "+f"(c[2]), "+f"(c[3])
        : "r"(a0), "r"(a1), "r"(a2), "r"(a3), "r"(b0), "r"(b1));
}
#define F2U(x) __float_as_uint(x)

// projection outputs (device-global scratch).
// g_Q, g_K: [b,s,h], h permuted within each 8-block (pos(j) = 2j if j<4 else 2(j-4)+1)
// g_V:      [b,h,s] transposed, s permuted within each 8-block (same map)
__device__ float g_Q[NB*SEQ*HID];
__device__ float g_K[NB*SEQ*HID];
__device__ float g_V[NB*SEQ*HID];

// ============================================================================
// Projection via tf32 mma.sync: Y = X @ W. CTA tile 128m x 128n, 256 threads,
// 8 warps (4 rg x 2 cg), warp tile 32x64. RN pre-rounded operands.
// Epilogue: Q/K permuted scalar stores; V staged through smem for a fully
// coalesced transposed store (g_V[h][s], s-pair-permuted).
// smem: Ws[128][260] | As 2x[128][36]   (T[128][140] reuses Ws region)
// ============================================================================
#define PWSTR 260
#define PASTR 36
#define P_OFF_A 33280
#define P_ASLOT 4608
#define P_SMEM ((33280 + 2*4608) * 4)
#define TSTR 140

__global__ void __launch_bounds__(256, 1)
proj_kernel(const float* __restrict__ q, const float* __restrict__ k, const float* __restrict__ v,
            const float* __restrict__ Wq, const float* __restrict__ Wk, const float* __restrict__ Wv)
{
    extern __shared__ float psm[];
    float* Ws = psm;
    float* As = psm + P_OFF_A;
    const uint32_t sA = smem_u32(As);

    const float* X; const float* W; float* Y;
    if (blockIdx.z == 0)      { X = q; W = Wq; Y = g_Q; }
    else if (blockIdx.z == 1) { X = k; W = Wk; Y = g_K; }
    else                      { X = v; W = Wv; Y = g_V; }
    const bool isV = (blockIdx.z == 2);

    const int tid = threadIdx.x;
    const int wid = tid >> 5, lane = tid & 31;
    const int rg = wid >> 1, cg = wid & 1;
    const int r0 = rg * 32, c0 = cg * 64;
    const int g = lane >> 2, tg = lane & 3;
    const int m0 = blockIdx.y * 128;
    const int n0 = blockIdx.x * 128;

    // issue A chunk 0 (slot 0)
    #pragma unroll
    for (int p = 0; p < 4; p++){
        int flat = tid + 256*p;
        int r = flat >> 3, j = flat & 7;
        CPASYNC16(sA + (r*PASTR + j*4)*4, (const void*)&X[(size_t)(m0 + r)*HID + j*4]);
    }
    CP_COMMIT();

    // W transpose into Ws[n][k], RN-rounded to tf32 (coalesced LDG rows)
    {
        const int n = (wid & 3)*32 + lane;
        const int kq0 = wid >> 2;
        #pragma unroll 4
        for (int i = 0; i < 32; i++){
            int kq = kq0 + 2*i;
            float a0 = W[(size_t)(kq*4+0)*HID + n0 + n];
            float a1 = W[(size_t)(kq*4+1)*HID + n0 + n];
            float a2 = W[(size_t)(kq*4+2)*HID + n0 + n];
            float a3 = W[(size_t)(kq*4+3)*HID + n0 + n];
            *(float4*)&Ws[n*PWSTR + kq*4] =
                make_float4(tf32r(a0), tf32r(a1), tf32r(a2), tf32r(a3));
        }
    }

    float acc[2][8][4];
    #pragma unroll
    for (int mi = 0; mi < 2; mi++)
        #pragma unroll
        for (int nt = 0; nt < 8; nt++)
            #pragma unroll
            for (int j = 0; j < 4; j++) acc[mi][nt][j] = 0.f;

    #pragma unroll 1
    for (int kc = 0; kc < 8; kc++){
        CP_WAIT(0);
        __syncthreads();           // publishes chunk kc (and Ws on kc==0)
        if (kc < 7){
            const uint32_t dst = sA + (((kc+1)&1)*P_ASLOT)*4;
            #pragma unroll
            for (int p = 0; p < 4; p++){
                int flat = tid + 256*p;
                int r = flat >> 3, j = flat & 7;
                CPASYNC16(dst + (r*PASTR + j*4)*4,
                          (const void*)&X[(size_t)(m0 + r)*HID + (kc+1)*32 + j*4]);
            }
            CP_COMMIT();
        }
        const float* Ab = As + (kc&1)*P_ASLOT;
        #pragma unroll
        for (int ks = 0; ks < 4; ks++){
            int kk = ks*8;
            uint32_t a[2][4];
            #pragma unroll
            for (int mi = 0; mi < 2; mi++){
                int base = (r0 + 16*mi + g)*PASTR + kk + tg;
                a[mi][0] = tf32u(Ab[base]);
                a[mi][1] = tf32u(Ab[base + 8*PASTR]);
                a[mi][2] = tf32u(Ab[base + 4]);
                a[mi][3] = tf32u(Ab[base + 8*PASTR + 4]);
            }
            #pragma unroll
            for (int nt = 0; nt < 8; nt++){
                int c = c0 + nt*8 + g;
                uint32_t b0 = F2U(Ws[c*PWSTR + kc*32 + kk + tg]);
                uint32_t b1 = F2U(Ws[c*PWSTR + kc*32 + kk + tg + 4]);
                mma8(acc[0][nt], a[0][0], a[0][1], a[0][2], a[0][3], b0, b1);
                mma8(acc[1][nt], a[1][0], a[1][1], a[1][2], a[1][3], b0, b1);
            }
        }
    }
    __syncthreads();   // all reads of Ws/As done before T overwrites (V path)

    // within-8 position map: pos(j) = 2j (j<4) else 2(j-4)+1
    const int pA = (tg < 2) ? 4*tg : 4*tg - 7;   // pos(2tg)
    const int pB = pA + 2;                       // pos(2tg+1)
    const int pg = (g < 4) ? 2*g : 2*(g-4) + 1;  // pos(g)

    if (!isV){
        // Q/K: h-pair-permuted scalar stores (full sectors per warp -> coalesced)
        #pragma unroll
        for (int mi = 0; mi < 2; mi++){
            int row = m0 + r0 + 16*mi + g;
            #pragma unroll
            for (int nt = 0; nt < 8; nt++){
                int colb = n0 + c0 + nt*8;
                Y[(size_t)row*HID + colb + pA]     = tf32r(acc[mi][nt][0]);
                Y[(size_t)row*HID + colb + pB]     = tf32r(acc[mi][nt][1]);
                Y[(size_t)(row+8)*HID + colb + pA] = tf32r(acc[mi][nt][2]);
                Y[(size_t)(row+8)*HID + colb + pB] = tf32r(acc[mi][nt][3]);
            }
        }
    } else {
        // V: stage O^T in smem (s-pair-permuted m positions), then coalesced STG
        float* T = psm;   // [128 n][TSTR], reuses Ws region
        #pragma unroll
        for (int mi = 0; mi < 2; mi++){
            int mb = r0 + 16*mi;
            #pragma unroll
            for (int nt = 0; nt < 8; nt++){
                int n = c0 + nt*8 + 2*tg;
                T[n*TSTR     + mb + pg]     = tf32r(acc[mi][nt][0]);
                T[(n+1)*TSTR + mb + pg]     = tf32r(acc[mi][nt][1]);
                T[n*TSTR     + mb + 8 + pg] = tf32r(acc[mi][nt][2]);
                T[(n+1)*TSTR + mb + 8 + pg] = tf32r(acc[mi][nt][3]);
            }
        }
        __syncthreads();
        const int bb = m0 >> 11;           // batch
        const int sbase = m0 & 2047;       // s offset within batch
        #pragma unroll 4
        for (int i = 0; i < 16; i++){
            int n = wid*16 + i;
            float4 vv = *(const float4*)&T[n*TSTR + 4*lane];
            *(float4*)&Y[(size_t)bb*SEQ*HID + (size_t)(n0 + n)*SEQ + sbase + 4*lane] = vv;
        }
    }
}

// ============================================================================
// Flash attention via mma.sync tf32 — 512 threads, 16 warps (4 rg x 4 cq).
// ALL fragment loads are LDS.64 pairs: Q/K pair-permuted in gmem, P permuted
// at softmax write, V transposed+permuted in gmem. K/V smem tiles [256][32]
// stride 40 (=8 mod 32 -> conflict-free LDS.64); Qs/Ps stride 264 (=8 mod 32).
// 2 slots, ONE sync per chunk. No-max softmax; P tf32-rounded.
// smem (floats): Qs[64][264] | Ps[64][264] | KV 2x10240 | lp[64][4]
// ============================================================================
#define QSTR 264
#define KVSTR 40
#define O_PS 16896
#define O_KV 33792
#define KVSLOT 10240
#define O_LP 54272
#define SMEM_ATTN (54528 * 4)

__global__ void __launch_bounds__(512, 1)
attn_kernel(const uint32_t* __restrict__ mask, float* __restrict__ out)
{
    extern __shared__ float sm[];
    float* Qs = sm;
    float* Ps = sm + O_PS;
    float* KV = sm + O_KV;
    float* lp = sm + O_LP;
    const uint32_t sQ  = smem_u32(Qs);
    const uint32_t sKV = smem_u32(KV);

    const int tid  = threadIdx.x;
    const int wid  = tid >> 5, lane = tid & 31;
    const int rg   = wid >> 2, cq = wid & 3;
    const int r0   = rg * 16;
    const int c0   = cq * 64;
    const int g    = lane >> 2, tg = lane & 3;
    const int b    = blockIdx.y;
    const int q0   = blockIdx.x * BM;

    const float* Qg = g_Q + (size_t)b*SEQ*HID;
    const float* Kg = g_K + (size_t)b*SEQ*HID;
    const float* Vg = g_V + (size_t)b*SEQ*HID;   // [h][s] layout
    const uint32_t* Mg = mask + (size_t)b*SEQ*SEQ;

    // ---- load Q tile [64][256] -> Qs[64][264] (already pair-permuted) ----
    #pragma unroll
    for (int p = 0; p < 8; p++){
        int idx = tid + 512*p;
        int r = idx >> 6, j = idx & 63;
        CPASYNC16(sQ + (r*QSTR + j*4)*4, (const void*)&Qg[(size_t)(q0 + r)*HID + j*4]);
    }
    CP_COMMIT();

    float oacc[8][4];
    #pragma unroll
    for (int i = 0; i < 8; i++)
        #pragma unroll
        for (int j = 0; j < 4; j++) oacc[i][j] = 0.f;
    float lsum0 = 0.f, lsum1 = 0.f;

    CP_WAIT(0);
    __syncthreads();

    for (int t = 0; t < SEQ/BN; t++){
        const int k0 = t * BN;

        // ===== QK^T: 8 hid-chunks of 32, 2 slots, ONE sync per chunk =====
        float sacc[8][4];
        #pragma unroll
        for (int i = 0; i < 8; i++)
            #pragma unroll
            for (int j = 0; j < 4; j++) sacc[i][j] = 0.f;

        // preamble: K chunk 0 -> slot 0 ([c=256][32] @ stride 40)
        #pragma unroll
        for (int p = 0; p < 4; p++){
            int flat = tid + 512*p;
            int c = flat >> 3, j = flat & 7;
            CPASYNC16(sKV + (c*KVSTR + j*4)*4,
                      (const void*)&Kg[(size_t)(k0 + c)*HID + j*4]);
        }
        CP_COMMIT();

        #pragma unroll 1
        for (int hc = 0; hc < 8; hc++){
            CP_WAIT(0);
            __syncthreads();       // chunk hc visible; everyone past compute hc-1
            if (hc < 7){
                const uint32_t dst = sKV + (((hc+1)&1)*KVSLOT)*4;
                #pragma unroll
                for (int p = 0; p < 4; p++){
                    int flat = tid + 512*p;
                    int c = flat >> 3, j = flat & 7;
                    CPASYNC16(dst + (c*KVSTR + j*4)*4,
                              (const void*)&Kg[(size_t)(k0 + c)*HID + (hc+1)*32 + j*4]);
                }
                CP_COMMIT();
            }
            const float* Kb = KV + (hc&1)*KVSLOT;
            #pragma unroll
            for (int ks = 0; ks < 4; ks++){
                int kk = ks*8;
                int hb = hc*32 + kk;
                float2 aA = *(const float2*)&Qs[(r0+g  )*QSTR + hb + 2*tg];
                float2 aB = *(const float2*)&Qs[(r0+g+8)*QSTR + hb + 2*tg];
                uint32_t a0 = F2U(aA.x), a1 = F2U(aB.x);
                uint32_t a2 = F2U(aA.y), a3 = F2U(aB.y);
                #pragma unroll
                for (int nt = 0; nt < 8; nt++){
                    int c = c0 + nt*8 + g;
                    float2 bb = *(const float2*)&Kb[c*KVSTR + kk + 2*tg];
                    mma8(sacc[nt], a0, a1, a2, a3, F2U(bb.x), F2U(bb.y));
                }
            }
        }

        // V chunk 0 -> slot 0 (Vt [h=256][32] @ stride 40; slot held K chunk 6)
        #pragma unroll
        for (int p = 0; p < 4; p++){
            int flat = tid + 512*p;
            int h = flat >> 3, j = flat & 7;
            CPASYNC16(sKV + (h*KVSTR + j*4)*4,
                      (const void*)&Vg[(size_t)h*SEQ + k0 + 4*j]);
        }
        CP_COMMIT();

        // ===== softmax (no max): P = mask ? 0 : tf32(exp(S/16)), s-permuted =====
        {
            const uint32_t* mr0 = Mg + (size_t)(q0 + r0 + g)*SEQ + k0 + c0 + 2*tg;
            const uint32_t* mr1 = mr0 + 8*SEQ;
            const int pA = (tg < 2) ? 4*tg : 4*tg - 7;
            #pragma unroll
            for (int nt = 0; nt < 8; nt++){
                uint2 m0v = *(const uint2*)(mr0 + nt*8);
                uint2 m1v = *(const uint2*)(mr1 + nt*8);
                float p00 = m0v.x ? 0.f : tf32r(__expf(sacc[nt][0] * QKSCALE));
                float p01 = m0v.y ? 0.f : tf32r(__expf(sacc[nt][1] * QKSCALE));
                float p10 = m1v.x ? 0.f : tf32r(__expf(sacc[nt][2] * QKSCALE));
                float p11 = m1v.y ? 0.f : tf32r(__expf(sacc[nt][3] * QKSCALE));
                lsum0 += p00 + p01;
                lsum1 += p10 + p11;
                int colb = c0 + nt*8;
                Ps[(r0+g  )*QSTR + colb + pA]     = p00;
                Ps[(r0+g  )*QSTR + colb + pA + 2] = p01;
                Ps[(r0+g+8)*QSTR + colb + pA]     = p10;
                Ps[(r0+g+8)*QSTR + colb + pA + 2] = p11;
            }
        }

        // ===== P @ V: 8 s-chunks of 32, 2 slots, ONE sync per chunk =====
        #pragma unroll 1
        for (int cc = 0; cc < 8; cc++){
            CP_WAIT(0);
            __syncthreads();       // V chunk cc visible; Ps published (cc==0)
            if (cc < 7){
                const uint32_t dst = sKV + (((cc+1)&1)*KVSLOT)*4;
                #pragma unroll
                for (int p = 0; p < 4; p++){
                    int flat = tid + 512*p;
                    int h = flat >> 3, j = flat & 7;
                    CPASYNC16(dst + (h*KVSTR + j*4)*4,
                              (const void*)&Vg[(size_t)h*SEQ + k0 + (cc+1)*32 + 4*j]);
                }
                CP_COMMIT();
            }
            const float* Vb = KV + (cc&1)*KVSLOT;
            #pragma unroll
            for (int ks = 0; ks < 4; ks++){
                int kk = ks*8;
                int cb = cc*32 + kk;
                float2 pAf = *(const float2*)&Ps[(r0+g  )*QSTR + cb + 2*tg];
                float2 pBf = *(const float2*)&Ps[(r0+g+8)*QSTR + cb + 2*tg];
                uint32_t a0 = F2U(pAf.x), a1 = F2U(pBf.x);
                uint32_t a2 = F2U(pAf.y), a3 = F2U(pBf.y);
                #pragma unroll
                for (int nt = 0; nt < 8; nt++){
                    int h = c0 + nt*8 + g;
                    float2 vv = *(const float2*)&Vb[h*KVSTR + kk + 2*tg];
                    mma8(oacc[nt], a0, a1, a2, a3, F2U(vv.x), F2U(vv.y));
                }
            }
        }
    }

    // ===== epilogue: l reduce + O /= l (fully-masked rows -> 0) =====
    lsum0 += __shfl_xor_sync(0xffffffffu, lsum0, 1);
    lsum0 += __shfl_xor_sync(0xffffffffu, lsum0, 2);
    lsum1 += __shfl_xor_sync(0xffffffffu, lsum1, 1);
    lsum1 += __shfl_xor_sync(0xffffffffu, lsum1, 2);
    if (tg == 0){
        lp[(r0+g  )*4 + cq] = lsum0;
        lp[(r0+g+8)*4 + cq] = lsum1;
    }
    __syncthreads();
    float l0 = lp[(r0+g  )*4] + lp[(r0+g  )*4 + 1] + lp[(r0+g  )*4 + 2] + lp[(r0+g  )*4 + 3];
    float l1 = lp[(r0+g+8)*4] + lp[(r0+g+8)*4 + 1] + lp[(r0+g+8)*4 + 2] + lp[(r0+g+8)*4 + 3];
    float inv0 = (l0 > 0.f) ? (1.f/l0) : 0.f;
    float inv1 = (l1 > 0.f) ? (1.f/l1) : 0.f;

    float* or0 = out + (size_t)(b*SEQ + q0 + r0 + g)*HID;
    float* or1 = or0 + 8*HID;
    #pragma unroll
    for (int nt = 0; nt < 8; nt++){
        int h = c0 + nt*8 + 2*tg;           // O columns are natural h
        *(float2*)&or0[h] = make_float2(oacc[nt][0]*inv0, oacc[nt][1]*inv0);
        *(float2*)&or1[h] = make_float2(oacc[nt][2]*inv1, oacc[nt][3]*inv1);
    }
}

// ============================================================================
extern "C" void kernel_launch(void* const* d_in, const int* in_sizes, int n_in,
                              void* d_out, int out_size)
{
    (void)in_sizes; (void)n_in; (void)out_size;
    const float* k  = (const float*)d_in[0];
    const float* q  = (const float*)d_in[1];
    const float* v  = (const float*)d_in[2];
    const uint32_t* mask = (const uint32_t*)d_in[3];
    const float* Wq = (const float*)d_in[4];
    const float* Wk = (const float*)d_in[5];
    const float* Wv = (const float*)d_in[6];
    float* out = (float*)d_out;

    cudaFuncSetAttribute(proj_kernel,
                         cudaFuncAttributeMaxDynamicSharedMemorySize, P_SMEM);
    proj_kernel<<<dim3(2, 128, 3), 256, P_SMEM>>>(q, k, v, Wq, Wk, Wv);

    cudaFuncSetAttribute(attn_kernel,
                         cudaFuncAttributeMaxDynamicSharedMemorySize, SMEM_ATTN);
    attn_kernel<<<dim3(SEQ/BM, NB), 512, SMEM_ATTN>>>(mask, out);
}